// round 6
// baseline (speedup 1.0000x reference)
#include <cuda_runtime.h>
#include <math.h>

// ---------------------------------------------------------------------------
// HumanPoseModule. Key algebraic identity: local_c = F_p^T F_c with
// F_j = root @ R_j  =>  local_c = R_p^T R_c (root cancels, orthonormal).
// So no FK accumulation at all: each joint's local rotation depends only on
// its parent's raw 6d->matrix and its own. Joint 0's local = root itself;
// children of root have local = R_c directly.
// ---------------------------------------------------------------------------

#define FDIV(a,b) __fdividef((a),(b))

// Octant-reduced atan2 for y >= 0 (result in [0, pi]); deg-11 minimax, ~2e-8.
__device__ __forceinline__ float fast_atan2_pos(float y, float x) {
    float ax = fabsf(x);
    float mn = fminf(y, ax);
    float mx = fmaxf(y, ax);
    float t  = FDIV(mn, mx);
    float t2 = t * t;
    float p = -0.0117212f;
    p = fmaf(p, t2,  0.05265332f);
    p = fmaf(p, t2, -0.11643287f);
    p = fmaf(p, t2,  0.19354346f);
    p = fmaf(p, t2, -0.33262347f);
    p = fmaf(p, t2,  0.99997726f);
    p = p * t;
    float r = (y > ax) ? (1.57079632679f - p) : p;
    if (x < 0.0f) r = 3.14159265359f - r;
    return r;
}

// 6D -> rotation matrix. A16: 16B-aligned load pattern, else 8B-aligned.
template <bool A16>
__device__ __forceinline__ void r6d_to_mat(const float* __restrict__ p, float R[9]) {
    float a1x, a1y, a1z, a2x, a2y, a2z;
    if (A16) {
        float4 v = *(const float4*)(p);
        float2 w = *(const float2*)(p + 4);
        a1x = v.x; a1y = v.y; a1z = v.z; a2x = v.w; a2y = w.x; a2z = w.y;
    } else {
        float2 v = *(const float2*)(p);
        float4 w = *(const float4*)(p + 2);
        a1x = v.x; a1y = v.y; a1z = w.x; a2x = w.y; a2y = w.z; a2z = w.w;
    }

    float in1 = rsqrtf(a1x*a1x + a1y*a1y + a1z*a1z);
    float b1x = a1x*in1, b1y = a1y*in1, b1z = a1z*in1;

    float dt = b1x*a2x + b1y*a2y + b1z*a2z;
    float b2x = a2x - dt*b1x, b2y = a2y - dt*b1y, b2z = a2z - dt*b1z;
    float in2 = rsqrtf(b2x*b2x + b2y*b2y + b2z*b2z);
    b2x *= in2; b2y *= in2; b2z *= in2;

    R[0]=b1x; R[1]=b1y; R[2]=b1z;
    R[3]=b2x; R[4]=b2y; R[5]=b2z;
    R[6] = b1y*b2z - b1z*b2y;
    R[7] = b1z*b2x - b1x*b2z;
    R[8] = b1x*b2y - b1y*b2x;
}

// C = A^T @ B   (local = parent^T @ child)
__device__ __forceinline__ void mat_tmul(const float A[9], const float B[9], float C[9]) {
#pragma unroll
    for (int i = 0; i < 3; i++)
#pragma unroll
        for (int j = 0; j < 3; j++)
            C[3*i+j] = A[0+i]*B[0+j] + A[3+i]*B[3+j] + A[6+i]*B[6+j];
}

// matrix -> axis-angle. Reference-equivalent:
//  - argmax over clamped squares == argmax over sqrts (monotone)
//  - sum of the four traces == 4 exactly => best >= 1 => fmax(qb,0.1)=qb
//  - sin(atan2(n,q0)) == n/sqrt(n^2+q0^2) (exact identity)
__device__ __forceinline__ void mat_to_aa(const float m[9], float* __restrict__ out) {
    float m00=m[0], m01=m[1], m02=m[2];
    float m10=m[3], m11=m[4], m12=m[5];
    float m20=m[6], m21=m[7], m22=m[8];

    float w0 = fmaxf(1.0f + m00 + m11 + m22, 0.0f);
    float w1 = fmaxf(1.0f + m00 - m11 - m22, 0.0f);
    float w2 = fmaxf(1.0f - m00 + m11 - m22, 0.0f);
    float w3 = fmaxf(1.0f - m00 - m11 + m22, 0.0f);

    int idx = 0; float best = w0;
    if (w1 > best) { best = w1; idx = 1; }
    if (w2 > best) { best = w2; idx = 2; }
    if (w3 > best) { best = w3; idx = 3; }

    float d21 = m21 - m12, d02 = m02 - m20, d10 = m10 - m01;
    float s10 = m10 + m01, s02 = m02 + m20, s21 = m21 + m12;

    float c0, c1, c2, c3;
    if (idx == 0)      { c0 = w0;  c1 = d21; c2 = d02; c3 = d10; }
    else if (idx == 1) { c0 = d21; c1 = w1;  c2 = s10; c3 = s02; }
    else if (idx == 2) { c0 = d02; c1 = s10; c2 = w2;  c3 = s21; }
    else               { c0 = d10; c1 = s02; c2 = s21; c3 = w3;  }

    float id = 0.5f * rsqrtf(best);       // == 0.5 / max(sqrt(best), 0.1)
    float q0 = c0*id, q1 = c1*id, q2 = c2*id, q3 = c3*id;

    float nrm2 = q1*q1 + q2*q2 + q3*q3;
    float nrm  = sqrtf(nrm2);
    float half = fast_atan2_pos(nrm, q0);
    float ang  = 2.0f * half;

    float scale;
    if (fabsf(ang) < 1e-6f) {
        scale = FDIV(1.0f, 0.5f - ang*ang*(1.0f/48.0f));
    } else {
        float len = sqrtf(nrm2 + q0*q0);
        scale = FDIV(ang * len, nrm);
    }
    out[0] = q1*scale; out[1] = q2*scale; out[2] = q3*scale;
}

__global__ void __launch_bounds__(256)
pose_kernel(const float* __restrict__ glb,   // (BT, 10, 6)
            const float* __restrict__ ori,   // (BT, 6, 6)
            float* __restrict__ out,         // (BT, 24, 3)
            int n)
{
    int i = blockIdx.x * blockDim.x + threadIdx.x;
    if (i >= n) return;

    const float* g  = glb + (size_t)i * 60;
    const float* o6 = ori + (size_t)i * 36;
    float* po = out + (size_t)i * 72;

    // Ignored joints {7,8,10,11,20,21,22,23} -> zero axis-angle.
    po[21]=0.f; po[22]=0.f; po[23]=0.f; po[24]=0.f; po[25]=0.f; po[26]=0.f;
    *(float2*)(po + 30) = make_float2(0.f, 0.f);
    *(float4*)(po + 32) = make_float4(0.f,0.f,0.f,0.f);
    *(float4*)(po + 60) = make_float4(0.f,0.f,0.f,0.f);
    *(float4*)(po + 64) = make_float4(0.f,0.f,0.f,0.f);
    *(float4*)(po + 68) = make_float4(0.f,0.f,0.f,0.f);

    float Rp[9], Rc[9], L[9];

    // joint 0: local = root
    r6d_to_mat<true>(o6 + 0, Rp);
    mat_to_aa(Rp, po + 0);

    // chain: 1 -> 4(sensor1).  local(1) = R1, local(4) = R1^T O1
    r6d_to_mat<true >(g + 0, Rp);   mat_to_aa(Rp, po + 3);
    r6d_to_mat<false>(o6 + 6, Rc);  mat_tmul(Rp, Rc, L);  mat_to_aa(L, po + 12);

    // chain: 2 -> 5(sensor2)
    r6d_to_mat<false>(g + 6, Rp);   mat_to_aa(Rp, po + 6);
    r6d_to_mat<true >(o6 + 12, Rc); mat_tmul(Rp, Rc, L);  mat_to_aa(L, po + 15);

    // spine: 3 -> 6 -> 9
    r6d_to_mat<true >(g + 12, Rp);  mat_to_aa(Rp, po + 9);          // joint 3
    r6d_to_mat<false>(g + 18, Rc);  mat_tmul(Rp, Rc, L);  mat_to_aa(L, po + 18); // 6
    float R9[9];
    r6d_to_mat<true >(g + 24, R9);  mat_tmul(Rc, R9, L);  mat_to_aa(L, po + 27); // 9

    // branch: 12 -> 15(sensor3)
    r6d_to_mat<false>(g + 30, Rp);  mat_tmul(R9, Rp, L);  mat_to_aa(L, po + 36); // 12
    r6d_to_mat<false>(o6 + 18, Rc); mat_tmul(Rp, Rc, L);  mat_to_aa(L, po + 45); // 15

    // branch: 13 -> 16 -> 18(sensor4)
    r6d_to_mat<true >(g + 36, Rp);  mat_tmul(R9, Rp, L);  mat_to_aa(L, po + 39); // 13
    r6d_to_mat<true >(g + 48, Rc);  mat_tmul(Rp, Rc, L);  mat_to_aa(L, po + 48); // 16
    r6d_to_mat<true >(o6 + 24, Rp); mat_tmul(Rc, Rp, L);  mat_to_aa(L, po + 54); // 18

    // branch: 14 -> 17 -> 19(sensor5)
    r6d_to_mat<false>(g + 42, Rp);  mat_tmul(R9, Rp, L);  mat_to_aa(L, po + 42); // 14
    r6d_to_mat<false>(g + 54, Rc);  mat_tmul(Rp, Rc, L);  mat_to_aa(L, po + 51); // 17
    r6d_to_mat<false>(o6 + 30, Rp); mat_tmul(Rc, Rp, L);  mat_to_aa(L, po + 57); // 19
}

extern "C" void kernel_launch(void* const* d_in, const int* in_sizes, int n_in,
                              void* d_out, int out_size) {
    const float* glb;
    const float* ori;
    if (in_sizes[0] >= in_sizes[1]) {
        glb = (const float*)d_in[0];
        ori = (const float*)d_in[1];
    } else {
        glb = (const float*)d_in[1];
        ori = (const float*)d_in[0];
    }
    int n = out_size / 72;

    const int threads = 256;
    const int blocks = (n + threads - 1) / threads;
    pose_kernel<<<blocks, threads>>>(glb, ori, (float*)d_out, n);
}

// round 8
// speedup vs baseline: 1.7732x; 1.7732x over previous
#include <cuda_runtime.h>
#include <math.h>

// ---------------------------------------------------------------------------
// HumanPoseModule. local_c = R_p^T R_c (root cancels; orthonormal).
// Smem-staged inputs (coalesced LDG.128, padded conflict-free AoS),
// output-sequential joint order with float4 store buffering.
// ---------------------------------------------------------------------------

#define FDIV(a,b) __fdividef((a),(b))

constexpr int TPB = 256;
constexpr int GS  = 61;   // padded glb stride (floats); 61 odd -> conflict-free
constexpr int OS  = 37;   // padded ori stride
constexpr int SMEM_BYTES = (TPB*GS + TPB*OS) * 4;   // 100,352 B

// Octant-reduced atan2 for y >= 0 (result in [0, pi]); deg-11 minimax, ~2e-8.
__device__ __forceinline__ float fast_atan2_pos(float y, float x) {
    float ax = fabsf(x);
    float mn = fminf(y, ax);
    float mx = fmaxf(y, ax);
    float t  = FDIV(mn, mx);
    float t2 = t * t;
    float p = -0.0117212f;
    p = fmaf(p, t2,  0.05265332f);
    p = fmaf(p, t2, -0.11643287f);
    p = fmaf(p, t2,  0.19354346f);
    p = fmaf(p, t2, -0.33262347f);
    p = fmaf(p, t2,  0.99997726f);
    p = p * t;
    float r = (y > ax) ? (1.57079632679f - p) : p;
    if (x < 0.0f) r = 3.14159265359f - r;
    return r;
}

// 6D (6 scalar smem floats) -> rotation matrix
__device__ __forceinline__ void r6d_to_mat(const float* __restrict__ p, float R[9]) {
    float a1x = p[0], a1y = p[1], a1z = p[2];
    float a2x = p[3], a2y = p[4], a2z = p[5];

    float in1 = rsqrtf(a1x*a1x + a1y*a1y + a1z*a1z);
    float b1x = a1x*in1, b1y = a1y*in1, b1z = a1z*in1;

    float dt = b1x*a2x + b1y*a2y + b1z*a2z;
    float b2x = a2x - dt*b1x, b2y = a2y - dt*b1y, b2z = a2z - dt*b1z;
    float in2 = rsqrtf(b2x*b2x + b2y*b2y + b2z*b2z);
    b2x *= in2; b2y *= in2; b2z *= in2;

    R[0]=b1x; R[1]=b1y; R[2]=b1z;
    R[3]=b2x; R[4]=b2y; R[5]=b2z;
    R[6] = b1y*b2z - b1z*b2y;
    R[7] = b1z*b2x - b1x*b2z;
    R[8] = b1x*b2y - b1y*b2x;
}

// C = A^T @ B
__device__ __forceinline__ void mat_tmul(const float A[9], const float B[9], float C[9]) {
#pragma unroll
    for (int i = 0; i < 3; i++)
#pragma unroll
        for (int j = 0; j < 3; j++)
            C[3*i+j] = A[0+i]*B[0+j] + A[3+i]*B[3+j] + A[6+i]*B[6+j];
}

// matrix -> axis-angle (reference-equivalent; see prior-round derivations)
__device__ __forceinline__ void mat_to_aa(const float m[9],
                                          float& o0, float& o1, float& o2) {
    float m00=m[0], m01=m[1], m02=m[2];
    float m10=m[3], m11=m[4], m12=m[5];
    float m20=m[6], m21=m[7], m22=m[8];

    float w0 = fmaxf(1.0f + m00 + m11 + m22, 0.0f);
    float w1 = fmaxf(1.0f + m00 - m11 - m22, 0.0f);
    float w2 = fmaxf(1.0f - m00 + m11 - m22, 0.0f);
    float w3 = fmaxf(1.0f - m00 - m11 + m22, 0.0f);

    int idx = 0; float best = w0;
    if (w1 > best) { best = w1; idx = 1; }
    if (w2 > best) { best = w2; idx = 2; }
    if (w3 > best) { best = w3; idx = 3; }

    float d21 = m21 - m12, d02 = m02 - m20, d10 = m10 - m01;
    float s10 = m10 + m01, s02 = m02 + m20, s21 = m21 + m12;

    float c0, c1, c2, c3;
    if (idx == 0)      { c0 = w0;  c1 = d21; c2 = d02; c3 = d10; }
    else if (idx == 1) { c0 = d21; c1 = w1;  c2 = s10; c3 = s02; }
    else if (idx == 2) { c0 = d02; c1 = s10; c2 = w2;  c3 = s21; }
    else               { c0 = d10; c1 = s02; c2 = s21; c3 = w3;  }

    float id = 0.5f * rsqrtf(best);     // best >= 1 (traces sum to 4)
    float q0 = c0*id, q1 = c1*id, q2 = c2*id, q3 = c3*id;

    float nrm2 = fmaxf(q1*q1 + q2*q2 + q3*q3, 1e-30f);
    float nrm  = nrm2 * rsqrtf(nrm2);
    float half = fast_atan2_pos(nrm, q0);
    float ang  = 2.0f * half;

    float scale;
    if (fabsf(ang) < 1e-6f) {
        scale = FDIV(1.0f, 0.5f - ang*ang*(1.0f/48.0f));
    } else {
        float l2  = nrm2 + q0*q0;           // ~0.25..inf, never 0
        float len = l2 * rsqrtf(l2);
        scale = FDIV(ang * len, nrm);
    }
    o0 = q1*scale; o1 = q2*scale; o2 = q3*scale;
}

__global__ void __launch_bounds__(TPB, 2)
pose_kernel(const float* __restrict__ glb,   // (BT, 10, 6)
            const float* __restrict__ ori,   // (BT, 6, 6)
            float* __restrict__ out,         // (BT, 24, 3)
            int n)
{
    extern __shared__ float smem[];
    float* sg = smem;             // [TPB][GS]
    float* so = smem + TPB*GS;    // [TPB][OS]

    int base = blockIdx.x * TPB;
    int samples = n - base; if (samples > TPB) samples = TPB;
    int t = threadIdx.x;

    // ---- stage glb: samples*60 floats, coalesced float4 ----
    {
        const float4* src = (const float4*)(glb + (size_t)base * 60);
        int nf4 = (samples * 60) >> 2;     // 60 % 4 == 0
        for (int j = t; j < nf4; j += TPB) {
            float4 v = src[j];
            int f = 4*j;
            int s = f/60, k = f - s*60;
            sg[s*GS + k] = v.x;
            if (++k == 60) { k = 0; ++s; } sg[s*GS + k] = v.y;
            if (++k == 60) { k = 0; ++s; } sg[s*GS + k] = v.z;
            if (++k == 60) { k = 0; ++s; } sg[s*GS + k] = v.w;
        }
    }
    // ---- stage ori: samples*36 floats ----
    {
        const float4* src = (const float4*)(ori + (size_t)base * 36);
        int nf4 = (samples * 36) >> 2;
        for (int j = t; j < nf4; j += TPB) {
            float4 v = src[j];
            int f = 4*j;
            int s = f/36, k = f - s*36;
            so[s*OS + k] = v.x;
            if (++k == 36) { k = 0; ++s; } so[s*OS + k] = v.y;
            if (++k == 36) { k = 0; ++s; } so[s*OS + k] = v.z;
            if (++k == 36) { k = 0; ++s; } so[s*OS + k] = v.w;
        }
    }
    __syncthreads();
    if (t >= samples) return;

    const float* gp = sg + t*GS;
    const float* op = so + t*OS;
    float* po = out + (size_t)(base + t) * 72;   // 288B-aligned -> 16B ok

    float A[9], B[9], C[9], L[9];
    float a0,a1,a2, b0,b1,b2, c0,c1,c2, d0,d1,d2;

    // ---- group 1: joints 0..3 ----
    // j0 = root; j1 = R1; j2 = R2; j3 = R3 (children of root: local == own R)
    r6d_to_mat(op + 0, L);  mat_to_aa(L, a0,a1,a2);
    r6d_to_mat(gp + 0, A);  mat_to_aa(A, b0,b1,b2);     // R1 (keep)
    r6d_to_mat(gp + 6, B);  mat_to_aa(B, c0,c1,c2);     // R2 (keep)
    r6d_to_mat(gp + 12, C); mat_to_aa(C, d0,d1,d2);     // R3 (keep)
    *(float4*)(po + 0) = make_float4(a0,a1,a2,b0);
    *(float4*)(po + 4) = make_float4(b1,b2,c0,c1);
    *(float4*)(po + 8) = make_float4(c2,d0,d1,d2);

    // ---- group 2: joints 4..7  (7 ignored -> 0) ----
    float T[9];
    r6d_to_mat(op + 6,  T); mat_tmul(A, T, L); mat_to_aa(L, a0,a1,a2);  // j4 = R1^T O1
    r6d_to_mat(op + 12, T); mat_tmul(B, T, L); mat_to_aa(L, b0,b1,b2);  // j5 = R2^T O2
    float R6[9];
    r6d_to_mat(gp + 18, R6); mat_tmul(C, R6, L); mat_to_aa(L, c0,c1,c2); // j6 = R3^T R6
    *(float4*)(po + 12) = make_float4(a0,a1,a2,b0);
    *(float4*)(po + 16) = make_float4(b1,b2,c0,c1);
    *(float4*)(po + 20) = make_float4(c2,0.f,0.f,0.f);

    // ---- group 3: joints 8..11 (8,10,11 ignored) ----
    float R9[9];
    r6d_to_mat(gp + 24, R9); mat_tmul(R6, R9, L); mat_to_aa(L, b0,b1,b2); // j9
    *(float4*)(po + 24) = make_float4(0.f,0.f,0.f,b0);
    *(float4*)(po + 28) = make_float4(b1,b2,0.f,0.f);
    *(float4*)(po + 32) = make_float4(0.f,0.f,0.f,0.f);

    // ---- group 4: joints 12..15 ----
    r6d_to_mat(gp + 30, A); mat_tmul(R9, A, L); mat_to_aa(L, a0,a1,a2);  // j12 (A=R12 keep)
    r6d_to_mat(gp + 36, B); mat_tmul(R9, B, L); mat_to_aa(L, b0,b1,b2);  // j13 (B=R13 keep)
    r6d_to_mat(gp + 42, C); mat_tmul(R9, C, L); mat_to_aa(L, c0,c1,c2);  // j14 (C=R14 keep)
    r6d_to_mat(op + 18, T); mat_tmul(A,  T, L); mat_to_aa(L, d0,d1,d2);  // j15 = R12^T O3
    *(float4*)(po + 36) = make_float4(a0,a1,a2,b0);
    *(float4*)(po + 40) = make_float4(b1,b2,c0,c1);
    *(float4*)(po + 44) = make_float4(c2,d0,d1,d2);

    // ---- group 5: joints 16..19 ----
    r6d_to_mat(gp + 48, A); mat_tmul(B, A, L); mat_to_aa(L, a0,a1,a2);   // j16 = R13^T R16 (A=R16)
    r6d_to_mat(gp + 54, B); mat_tmul(C, B, L); mat_to_aa(L, b0,b1,b2);   // j17 = R14^T R17 (B=R17)
    r6d_to_mat(op + 24, T); mat_tmul(A, T, L); mat_to_aa(L, c0,c1,c2);   // j18 = R16^T O4
    r6d_to_mat(op + 30, T); mat_tmul(B, T, L); mat_to_aa(L, d0,d1,d2);   // j19 = R17^T O5
    *(float4*)(po + 48) = make_float4(a0,a1,a2,b0);
    *(float4*)(po + 52) = make_float4(b1,b2,c0,c1);
    *(float4*)(po + 56) = make_float4(c2,d0,d1,d2);

    // ---- group 6: joints 20..23 (all ignored) ----
    *(float4*)(po + 60) = make_float4(0.f,0.f,0.f,0.f);
    *(float4*)(po + 64) = make_float4(0.f,0.f,0.f,0.f);
    *(float4*)(po + 68) = make_float4(0.f,0.f,0.f,0.f);
}

extern "C" void kernel_launch(void* const* d_in, const int* in_sizes, int n_in,
                              void* d_out, int out_size) {
    const float* glb;
    const float* ori;
    if (in_sizes[0] >= in_sizes[1]) {
        glb = (const float*)d_in[0];
        ori = (const float*)d_in[1];
    } else {
        glb = (const float*)d_in[1];
        ori = (const float*)d_in[0];
    }
    int n = out_size / 72;

    static bool attr_set = false;
    if (!attr_set) {
        cudaFuncSetAttribute(pose_kernel,
                             cudaFuncAttributeMaxDynamicSharedMemorySize,
                             SMEM_BYTES);
        attr_set = true;
    }

    const int blocks = (n + TPB - 1) / TPB;
    pose_kernel<<<blocks, TPB, SMEM_BYTES>>>(glb, ori, (float*)d_out, n);
}

// round 10
// speedup vs baseline: 1.9630x; 1.1071x over previous
#include <cuda_runtime.h>
#include <math.h>

// ---------------------------------------------------------------------------
// HumanPoseModule. local_c = R_p^T R_c (root cancels; orthonormal).
// glb staged in smem (pure float4 memcpy, unpadded stride-60: conflict-free
// for vector LDS); ori loaded direct with aligned float4/float2 pattern.
// Output-sequential joint order, float4 store buffering.
// ---------------------------------------------------------------------------

#define FDIV(a,b) __fdividef((a),(b))

constexpr int TPB = 256;
constexpr int SMEM_BYTES = TPB * 60 * 4;   // 61,440 B -> 3 blocks/SM

// Octant-reduced atan2 for y >= 0 (result in [0, pi]); deg-11 minimax, ~2e-8.
__device__ __forceinline__ float fast_atan2_pos(float y, float x) {
    float ax = fabsf(x);
    float mn = fminf(y, ax);
    float mx = fmaxf(y, ax);
    float t  = FDIV(mn, mx);
    float t2 = t * t;
    float p = -0.0117212f;
    p = fmaf(p, t2,  0.05265332f);
    p = fmaf(p, t2, -0.11643287f);
    p = fmaf(p, t2,  0.19354346f);
    p = fmaf(p, t2, -0.33262347f);
    p = fmaf(p, t2,  0.99997726f);
    p = p * t;
    float r = (y > ax) ? (1.57079632679f - p) : p;
    if (x < 0.0f) r = 3.14159265359f - r;
    return r;
}

__device__ __forceinline__ void r6d_core(float a1x, float a1y, float a1z,
                                         float a2x, float a2y, float a2z,
                                         float R[9]) {
    float in1 = rsqrtf(a1x*a1x + a1y*a1y + a1z*a1z);
    float b1x = a1x*in1, b1y = a1y*in1, b1z = a1z*in1;

    float dt = b1x*a2x + b1y*a2y + b1z*a2z;
    float b2x = a2x - dt*b1x, b2y = a2y - dt*b1y, b2z = a2z - dt*b1z;
    float in2 = rsqrtf(b2x*b2x + b2y*b2y + b2z*b2z);
    b2x *= in2; b2y *= in2; b2z *= in2;

    R[0]=b1x; R[1]=b1y; R[2]=b1z;
    R[3]=b2x; R[4]=b2y; R[5]=b2z;
    R[6] = b1y*b2z - b1z*b2y;
    R[7] = b1z*b2x - b1x*b2z;
    R[8] = b1x*b2y - b1y*b2x;
}

// Vector-load 6 floats. A16: offset is 16B aligned (float4+float2),
// else 8B aligned (float2 + float4 at +2). Works for smem and gmem pointers.
template <bool A16>
__device__ __forceinline__ void r6d_to_mat(const float* __restrict__ p, float R[9]) {
    float a1x, a1y, a1z, a2x, a2y, a2z;
    if (A16) {
        float4 v = *(const float4*)(p);
        float2 w = *(const float2*)(p + 4);
        a1x = v.x; a1y = v.y; a1z = v.z; a2x = v.w; a2y = w.x; a2z = w.y;
    } else {
        float2 v = *(const float2*)(p);
        float4 w = *(const float4*)(p + 2);
        a1x = v.x; a1y = v.y; a1z = w.x; a2x = w.y; a2y = w.z; a2z = w.w;
    }
    r6d_core(a1x, a1y, a1z, a2x, a2y, a2z, R);
}

// C = A^T @ B
__device__ __forceinline__ void mat_tmul(const float A[9], const float B[9], float C[9]) {
#pragma unroll
    for (int i = 0; i < 3; i++)
#pragma unroll
        for (int j = 0; j < 3; j++)
            C[3*i+j] = A[0+i]*B[0+j] + A[3+i]*B[3+j] + A[6+i]*B[6+j];
}

// matrix -> axis-angle (reference-equivalent; see prior-round derivations)
__device__ __forceinline__ void mat_to_aa(const float m[9],
                                          float& o0, float& o1, float& o2) {
    float m00=m[0], m01=m[1], m02=m[2];
    float m10=m[3], m11=m[4], m12=m[5];
    float m20=m[6], m21=m[7], m22=m[8];

    float w0 = fmaxf(1.0f + m00 + m11 + m22, 0.0f);
    float w1 = fmaxf(1.0f + m00 - m11 - m22, 0.0f);
    float w2 = fmaxf(1.0f - m00 + m11 - m22, 0.0f);
    float w3 = fmaxf(1.0f - m00 - m11 + m22, 0.0f);

    int idx = 0; float best = w0;
    if (w1 > best) { best = w1; idx = 1; }
    if (w2 > best) { best = w2; idx = 2; }
    if (w3 > best) { best = w3; idx = 3; }

    float d21 = m21 - m12, d02 = m02 - m20, d10 = m10 - m01;
    float s10 = m10 + m01, s02 = m02 + m20, s21 = m21 + m12;

    float c0, c1, c2, c3;
    if (idx == 0)      { c0 = w0;  c1 = d21; c2 = d02; c3 = d10; }
    else if (idx == 1) { c0 = d21; c1 = w1;  c2 = s10; c3 = s02; }
    else if (idx == 2) { c0 = d02; c1 = s10; c2 = w2;  c3 = s21; }
    else               { c0 = d10; c1 = s02; c2 = s21; c3 = w3;  }

    float id = 0.5f * rsqrtf(best);     // best >= 1 (traces sum to 4)
    float q0 = c0*id, q1 = c1*id, q2 = c2*id, q3 = c3*id;

    float nrm2 = fmaxf(q1*q1 + q2*q2 + q3*q3, 1e-30f);
    float nrm  = nrm2 * rsqrtf(nrm2);
    float half = fast_atan2_pos(nrm, q0);
    float ang  = 2.0f * half;

    float scale;
    if (fabsf(ang) < 1e-6f) {
        scale = FDIV(1.0f, 0.5f - ang*ang*(1.0f/48.0f));
    } else {
        float l2  = nrm2 + q0*q0;           // >= 0.25, never 0
        float len = l2 * rsqrtf(l2);
        scale = FDIV(ang * len, nrm);
    }
    o0 = q1*scale; o1 = q2*scale; o2 = q3*scale;
}

__global__ void __launch_bounds__(TPB, 3)
pose_kernel(const float* __restrict__ glb,   // (BT, 10, 6)
            const float* __restrict__ ori,   // (BT, 6, 6)
            float* __restrict__ out,         // (BT, 24, 3)
            int n)
{
    extern __shared__ float sg[];   // [TPB][60] unpadded

    int base = blockIdx.x * TPB;
    int samples = n - base; if (samples > TPB) samples = TPB;
    int t = threadIdx.x;

    // ---- stage glb: straight float4 memcpy (coalesced, no remap) ----
    {
        const float4* __restrict__ src = (const float4*)(glb + (size_t)base * 60);
        float4* dst = (float4*)sg;
        int nf4 = samples * 15;           // 60/4 per sample
#pragma unroll 4
        for (int j = t; j < nf4; j += TPB) dst[j] = src[j];
    }
    __syncthreads();
    if (t >= samples) return;

    const float* gp = sg + t * 60;                    // t*60 ≡ 0 (mod 4) floats
    const float* op = ori + (size_t)(base + t) * 36;  // 144B-aligned base
    float* po = out + (size_t)(base + t) * 72;        // 288B-aligned base

    float A[9], B[9], C[9], L[9], T[9];
    float a0,a1,a2, b0,b1,b2, c0,c1,c2, d0,d1,d2;

    // ---- group 1: joints 0..3 (children of root: local == own R) ----
    r6d_to_mat<true >(op + 0, L);  mat_to_aa(L, a0,a1,a2);   // j0 = root
    r6d_to_mat<true >(gp + 0, A);  mat_to_aa(A, b0,b1,b2);   // j1 = R1 (keep)
    r6d_to_mat<false>(gp + 6, B);  mat_to_aa(B, c0,c1,c2);   // j2 = R2 (keep)
    r6d_to_mat<true >(gp + 12, C); mat_to_aa(C, d0,d1,d2);   // j3 = R3 (keep)
    *(float4*)(po + 0) = make_float4(a0,a1,a2,b0);
    *(float4*)(po + 4) = make_float4(b1,b2,c0,c1);
    *(float4*)(po + 8) = make_float4(c2,d0,d1,d2);

    // ---- group 2: joints 4..7 (7 ignored) ----
    r6d_to_mat<false>(op + 6,  T); mat_tmul(A, T, L); mat_to_aa(L, a0,a1,a2); // j4 = R1^T O1
    r6d_to_mat<true >(op + 12, T); mat_tmul(B, T, L); mat_to_aa(L, b0,b1,b2); // j5 = R2^T O2
    float R6[9];
    r6d_to_mat<false>(gp + 18, R6); mat_tmul(C, R6, L); mat_to_aa(L, c0,c1,c2); // j6 = R3^T R6
    *(float4*)(po + 12) = make_float4(a0,a1,a2,b0);
    *(float4*)(po + 16) = make_float4(b1,b2,c0,c1);
    *(float4*)(po + 20) = make_float4(c2,0.f,0.f,0.f);

    // ---- group 3: joints 8..11 (8,10,11 ignored) ----
    float R9[9];
    r6d_to_mat<true >(gp + 24, R9); mat_tmul(R6, R9, L); mat_to_aa(L, b0,b1,b2); // j9
    *(float4*)(po + 24) = make_float4(0.f,0.f,0.f,b0);
    *(float4*)(po + 28) = make_float4(b1,b2,0.f,0.f);
    *(float4*)(po + 32) = make_float4(0.f,0.f,0.f,0.f);

    // ---- group 4: joints 12..15 ----
    r6d_to_mat<false>(gp + 30, A); mat_tmul(R9, A, L); mat_to_aa(L, a0,a1,a2); // j12 (A=R12)
    r6d_to_mat<true >(gp + 36, B); mat_tmul(R9, B, L); mat_to_aa(L, b0,b1,b2); // j13 (B=R13)
    r6d_to_mat<false>(gp + 42, C); mat_tmul(R9, C, L); mat_to_aa(L, c0,c1,c2); // j14 (C=R14)
    r6d_to_mat<false>(op + 18, T); mat_tmul(A,  T, L); mat_to_aa(L, d0,d1,d2); // j15 = R12^T O3
    *(float4*)(po + 36) = make_float4(a0,a1,a2,b0);
    *(float4*)(po + 40) = make_float4(b1,b2,c0,c1);
    *(float4*)(po + 44) = make_float4(c2,d0,d1,d2);

    // ---- group 5: joints 16..19 ----
    r6d_to_mat<true >(gp + 48, A); mat_tmul(B, A, L); mat_to_aa(L, a0,a1,a2);  // j16 = R13^T R16
    r6d_to_mat<false>(gp + 54, B); mat_tmul(C, B, L); mat_to_aa(L, b0,b1,b2);  // j17 = R14^T R17
    r6d_to_mat<true >(op + 24, T); mat_tmul(A, T, L); mat_to_aa(L, c0,c1,c2);  // j18 = R16^T O4
    r6d_to_mat<false>(op + 30, T); mat_tmul(B, T, L); mat_to_aa(L, d0,d1,d2);  // j19 = R17^T O5
    *(float4*)(po + 48) = make_float4(a0,a1,a2,b0);
    *(float4*)(po + 52) = make_float4(b1,b2,c0,c1);
    *(float4*)(po + 56) = make_float4(c2,d0,d1,d2);

    // ---- group 6: joints 20..23 (all ignored) ----
    *(float4*)(po + 60) = make_float4(0.f,0.f,0.f,0.f);
    *(float4*)(po + 64) = make_float4(0.f,0.f,0.f,0.f);
    *(float4*)(po + 68) = make_float4(0.f,0.f,0.f,0.f);
}

extern "C" void kernel_launch(void* const* d_in, const int* in_sizes, int n_in,
                              void* d_out, int out_size) {
    const float* glb;
    const float* ori;
    if (in_sizes[0] >= in_sizes[1]) {
        glb = (const float*)d_in[0];
        ori = (const float*)d_in[1];
    } else {
        glb = (const float*)d_in[1];
        ori = (const float*)d_in[0];
    }
    int n = out_size / 72;

    static bool attr_set = false;
    if (!attr_set) {
        cudaFuncSetAttribute(pose_kernel,
                             cudaFuncAttributeMaxDynamicSharedMemorySize,
                             SMEM_BYTES);
        attr_set = true;
    }

    const int blocks = (n + TPB - 1) / TPB;
    pose_kernel<<<blocks, TPB, SMEM_BYTES>>>(glb, ori, (float*)d_out, n);
}